// round 15
// baseline (speedup 1.0000x reference)
#include <cuda_runtime.h>
#include <cuda_fp16.h>
#include <cstdint>
#include <cstddef>

#define D_DIM 1024
#define ROWS  4096   // B*S

// ------------------------- device scratch -------------------------
__device__ __half g_Vh  [ROWS * D_DIM];     // fp16(value)
__device__ __half g_Aoh [D_DIM * D_DIM];    // fp16(Wo)      [m][k]
__device__ __half g_Bvh [D_DIM * D_DIM];    // fp16(Wv^T)    [n][k]
__device__ __half g_Whi [D_DIM * D_DIM];    // fp16(W = Wo@Wv) [n][k]
__device__ float  g_bias[D_DIM];            // Wo@bv + bo

// ------------------------- helpers -------------------------
__device__ __forceinline__ uint32_t smem_u32(const void* p) {
    uint32_t a;
    asm("{ .reg .u64 t; cvta.to.shared.u64 t, %1; cvt.u32.u64 %0, t; }"
        : "=r"(a) : "l"(p));
    return a;
}

__device__ __forceinline__ void ldmatrix_x4(uint32_t* r, uint32_t addr) {
    asm volatile("ldmatrix.sync.aligned.m8n8.x4.shared.b16 {%0,%1,%2,%3}, [%4];"
                 : "=r"(r[0]), "=r"(r[1]), "=r"(r[2]), "=r"(r[3]) : "r"(addr));
}

__device__ __forceinline__ void mma_f16(float* d, const uint32_t* a,
                                        const uint32_t* b) {
    asm volatile(
        "mma.sync.aligned.m16n8k16.row.col.f32.f16.f16.f32 "
        "{%0,%1,%2,%3}, {%4,%5,%6,%7}, {%8,%9}, {%0,%1,%2,%3};"
        : "+f"(d[0]), "+f"(d[1]), "+f"(d[2]), "+f"(d[3])
        : "r"(a[0]), "r"(a[1]), "r"(a[2]), "r"(a[3]), "r"(b[0]), "r"(b[1]));
}

__device__ __forceinline__ void cp_async16(uint32_t dst, const void* src) {
    asm volatile("cp.async.cg.shared.global [%0], [%1], 16;"
                 :: "r"(dst), "l"(src) : "memory");
}

// PDL: allow dependent grid to begin launching (producer side, LATE placement)
__device__ __forceinline__ void pdl_trigger() {
    asm volatile("griddepcontrol.launch_dependents;" ::: "memory");
}
// PDL: block until producer grid's memory is fully visible (consumer side).
// No-op if this grid was not launched as a programmatic dependent.
__device__ __forceinline__ void pdl_wait() {
    asm volatile("griddepcontrol.wait;" ::: "memory");
}

// ------------------------- weight conversions (stream 0) ------------------
// bid < 1024: Wo row convert + bias GEMV.  bid >= 1024: Wv 32x32 transpose.
__global__ void __launch_bounds__(256)
convert_weights(const float* __restrict__ Wo, const float* __restrict__ bv,
                const float* __restrict__ bo, const float* __restrict__ Wv,
                __half* __restrict__ Aoh, __half* __restrict__ Bvh) {
    __shared__ float sm[33 * 32];
    const int bid = blockIdx.x;
    const int tid = threadIdx.x;

    if (bid < 1024) {
        const int row = bid;
        float4 a = ((const float4*)(Wo + (size_t)row * D_DIM))[tid];
        float4 b = ((const float4*)bv)[tid];
        __half2 h0(__float2half(a.x), __float2half(a.y));
        __half2 h1(__float2half(a.z), __float2half(a.w));
        uint2 pk = {*reinterpret_cast<uint32_t*>(&h0),
                    *reinterpret_cast<uint32_t*>(&h1)};
        ((uint2*)(Aoh + (size_t)row * D_DIM))[tid] = pk;
        float s = a.x * b.x + a.y * b.y + a.z * b.z + a.w * b.w;
        #pragma unroll
        for (int o = 16; o > 0; o >>= 1)
            s += __shfl_down_sync(0xFFFFFFFFu, s, o);
        if ((tid & 31) == 0) sm[tid >> 5] = s;
        __syncthreads();
        if (tid < 8) {
            s = sm[tid];
            #pragma unroll
            for (int o = 4; o > 0; o >>= 1)
                s += __shfl_down_sync(0xFFu, s, o);
            if (tid == 0) g_bias[row] = s + bo[row];
        }
    } else {
        const int t  = bid - 1024;
        const int bx = t & 31, by = t >> 5;
        const int tx = tid & 31, ty = tid >> 5;      // 32 x 8
        const int x = bx * 32 + tx;
        const int y = by * 32;
        #pragma unroll
        for (int j = ty; j < 32; j += 8)
            sm[j * 33 + tx] = Wv[(size_t)(y + j) * D_DIM + x];
        __syncthreads();
        const int ox  = by * 32 + tx;
        const int oyb = bx * 32;
        #pragma unroll
        for (int j = ty; j < 32; j += 8)
            Bvh[(size_t)(oyb + j) * D_DIM + ox] = __float2half(sm[tx * 33 + j]);
    }

    // Late trigger: GEMM1 begins launching as this grid drains.
    pdl_trigger();
}

// ------------------------- V convert (forked stream) ----------------------
__global__ void __launch_bounds__(256)
vconv(const float4* __restrict__ value, uint2* __restrict__ Vh2) {
    const int base = blockIdx.x * 512 + threadIdx.x;
    #pragma unroll
    for (int u = 0; u < 2; u++) {
        const int i = base + u * 256;
        float4 x = value[i];
        __half2 h0(__float2half(x.x), __float2half(x.y));
        __half2 h1(__float2half(x.z), __float2half(x.w));
        uint2 pk = {*reinterpret_cast<uint32_t*>(&h0),
                    *reinterpret_cast<uint32_t*>(&h1)};
        Vh2[i] = pk;
    }
}

// ------------------------- NT GEMM (mma.sync fp16, fp32 accum) ------------
// C[m][n] = sum_k A0[m,k] * B0[n,k]
// CTA tile BT x BT; warp tile WM x WN; BK=64; STAGES-deep cp.async.
// SPLITOUT: epilogue writes fp16(result) to Chi instead of fp32 C (+bias).
#define BKK   64
#define PITCH 144                            // 128B payload + 16B pad

template <int BT, int WM, int WN, int STAGES, bool SPLITOUT>
__global__ void __launch_bounds__((BT / WM) * (BT / WN) * 32, 2)
gemm_nt(const __half* __restrict__ A0, const __half* __restrict__ B0,
        float* __restrict__ C, __half* __restrict__ Chi,
        const float* __restrict__ bias) {
    constexpr int NWX     = BT / WN;         // warps along N
    constexpr int MI      = WM / 16;
    constexpr int NI      = WN / 8;
    constexpr int NJ      = WN / 16;
    constexpr int TPB     = BT * PITCH;
    constexpr int STAGE_B = 2 * TPB;
    constexpr int NT      = (BT / WM) * NWX * 32;
    constexpr int CHK     = (BT * 8) / NT;   // 16B chunks / thread / tile
    constexpr int T       = D_DIM / BKK;     // 16 k-tiles

    extern __shared__ __align__(128) char smem[];
    const uint32_t sbase = smem_u32(smem);

    const int tid = threadIdx.x;
    const int wid = tid >> 5;
    const int lid = tid & 31;
    const int wm  = wid / NWX;
    const int wn  = wid % NWX;
    const int m0  = blockIdx.y * BT;
    const int n0  = blockIdx.x * BT;

    const __half* gpA = A0 + (size_t)m0 * D_DIM;
    const __half* gpB = B0 + (size_t)n0 * D_DIM;

    // ldmatrix lane geometry
    const int mat   = lid >> 3;
    const int mrow  = ((mat & 1) << 3) + (lid & 7);
    const int mcolb = (mat >> 1) << 4;

    float acc[MI][NI][4];
    #pragma unroll
    for (int i = 0; i < MI; i++)
        #pragma unroll
        for (int j = 0; j < NI; j++)
            #pragma unroll
            for (int q = 0; q < 4; q++) acc[i][j][q] = 0.f;

    // Consumer side: producer's memory fully visible after this returns
    // (no-op when launched without programmatic dependency).
    pdl_wait();

    auto issue = [&](int t) {
        const uint32_t sb = sbase + (t % STAGES) * STAGE_B;
        const int k0 = t * BKK;
        #pragma unroll
        for (int i = 0; i < CHK; i++) {
            const int c = tid + i * NT;
            const int r = c >> 3, cc = c & 7;
            cp_async16(sb + r * PITCH + cc * 16,
                       gpA + (size_t)r * D_DIM + k0 + cc * 8);
            cp_async16(sb + TPB + r * PITCH + cc * 16,
                       gpB + (size_t)r * D_DIM + k0 + cc * 8);
        }
    };

    #pragma unroll
    for (int t = 0; t < STAGES - 1; t++) {
        issue(t);
        asm volatile("cp.async.commit_group;" ::: "memory");
    }

    for (int t = 0; t < T; t++) {
        asm volatile("cp.async.wait_group %0;" :: "n"(STAGES - 2) : "memory");
        __syncthreads();

        if (t + STAGES - 1 < T) issue(t + STAGES - 1);
        asm volatile("cp.async.commit_group;" ::: "memory");

        const uint32_t bA = sbase + (t % STAGES) * STAGE_B;
        const uint32_t bB = bA + TPB;

        #pragma unroll
        for (int kk = 0; kk < BKK / 16; kk++) {
            uint32_t a0[MI][4];
            uint32_t b0[NI][2];
            #pragma unroll
            for (int mi = 0; mi < MI; mi++) {
                uint32_t roff = (uint32_t)(wm * WM + mi * 16 + mrow) * PITCH +
                                mcolb + kk * 32;
                ldmatrix_x4(a0[mi], bA + roff);
            }
            #pragma unroll
            for (int nj = 0; nj < NJ; nj++) {
                uint32_t roff = (uint32_t)(wn * WN + nj * 16 + mrow) * PITCH +
                                mcolb + kk * 32;
                uint32_t r[4];
                ldmatrix_x4(r, bB + roff);
                b0[nj * 2][0]     = r[0]; b0[nj * 2][1]     = r[2];
                b0[nj * 2 + 1][0] = r[1]; b0[nj * 2 + 1][1] = r[3];
            }
            #pragma unroll
            for (int mi = 0; mi < MI; mi++)
                #pragma unroll
                for (int ni = 0; ni < NI; ni++)
                    mma_f16(acc[mi][ni], a0[mi], b0[ni]);
        }
        __syncthreads();
    }

    // Late trigger: only the epilogue remains.
    pdl_trigger();

    // ---- epilogue ----
    const int trow = lid >> 2;
    const int tcol = (lid & 3) * 2;
    #pragma unroll
    for (int mi = 0; mi < MI; mi++) {
        const int row = m0 + wm * WM + mi * 16 + trow;
        #pragma unroll
        for (int ni = 0; ni < NI; ni++) {
            const int col = n0 + wn * WN + ni * 8 + tcol;
            if (SPLITOUT) {
                #pragma unroll
                for (int h = 0; h < 2; h++) {
                    const int rr = row + h * 8;
                    __half2 hv(__float2half(acc[mi][ni][h * 2 + 0]),
                               __float2half(acc[mi][ni][h * 2 + 1]));
                    *reinterpret_cast<__half2*>(&Chi[(size_t)rr * D_DIM + col]) = hv;
                }
            } else {
                float b0v = bias[col], b1v = bias[col + 1];
                float2 v0 = {acc[mi][ni][0] + b0v, acc[mi][ni][1] + b1v};
                float2 v1 = {acc[mi][ni][2] + b0v, acc[mi][ni][3] + b1v};
                *reinterpret_cast<float2*>(&C[(size_t)row * D_DIM + col]) = v0;
                *reinterpret_cast<float2*>(&C[(size_t)(row + 8) * D_DIM + col]) = v1;
            }
        }
    }
}

// ------------------------- host launcher -------------------------
#define SMEM_G1 (3 * 2 * 64 * PITCH)    // 55296  (3 stages, 2 tiles, BT=64)
#define SMEM_G2 (3 * 2 * 128 * PITCH)   // 110592 (3 stages, 2 tiles, BT=128)

extern "C" void kernel_launch(void* const* d_in, const int* in_sizes, int n_in,
                              void* d_out, int out_size) {
    // 0 query, 1 key, 2 value, 3 mask, 4 Wq, 5 bq, 6 Wk, 7 bk, 8 Wv, 9 bv, 10 Wo, 11 bo
    const float* value = (const float*)d_in[2];
    const float* Wv    = (const float*)d_in[8];
    const float* bv    = (const float*)d_in[9];
    const float* Wo    = (const float*)d_in[10];
    const float* bo    = (const float*)d_in[11];
    float* out = (float*)d_out;

    void *pVh, *pAoh, *pBvh, *pWhi, *pbias;
    cudaGetSymbolAddress(&pVh, g_Vh);
    cudaGetSymbolAddress(&pAoh, g_Aoh);
    cudaGetSymbolAddress(&pBvh, g_Bvh);
    cudaGetSymbolAddress(&pWhi, g_Whi);
    cudaGetSymbolAddress(&pbias, g_bias);

    cudaFuncSetAttribute((const void*)gemm_nt<64, 32, 32, 3, true>,
                         cudaFuncAttributeMaxDynamicSharedMemorySize, SMEM_G1);
    cudaFuncSetAttribute((const void*)gemm_nt<128, 64, 64, 3, false>,
                         cudaFuncAttributeMaxDynamicSharedMemorySize, SMEM_G2);

    // One-time host infra (streams/events are not device memory; the device
    // work recorded per call is identical every call).
    static cudaStream_t s1 = nullptr;
    static cudaEvent_t  eFork = nullptr, eJoin = nullptr;
    if (s1 == nullptr) {
        cudaStreamCreateWithFlags(&s1, cudaStreamNonBlocking);
        cudaEventCreateWithFlags(&eFork, cudaEventDisableTiming);
        cudaEventCreateWithFlags(&eJoin, cudaEventDisableTiming);
    }

    // ---- fork: V convert runs concurrently with weight convert + GEMM1 ----
    cudaEventRecord(eFork, 0);
    cudaStreamWaitEvent(s1, eFork, 0);
    vconv<<<2048, 256, 0, s1>>>((const float4*)value, (uint2*)pVh);
    cudaEventRecord(eJoin, s1);

    // ---- main chain on stream 0 ----
    convert_weights<<<2048, 256>>>(Wo, bv, bo, Wv,
                                   (__half*)pAoh, (__half*)pBvh);

    // GEMM1 with PDL (overlaps convert_weights' drain)
    {
        cudaLaunchAttribute pdlAttr[1];
        pdlAttr[0].id = cudaLaunchAttributeProgrammaticStreamSerialization;
        pdlAttr[0].val.programmaticStreamSerializationAllowed = 1;
        cudaLaunchConfig_t cfg = {};
        cfg.gridDim  = dim3(D_DIM / 64, D_DIM / 64, 1);
        cfg.blockDim = dim3(128, 1, 1);
        cfg.dynamicSmemBytes = SMEM_G1;
        cfg.stream = 0;
        cfg.attrs = pdlAttr;
        cfg.numAttrs = 1;
        cudaLaunchKernelEx(&cfg, gemm_nt<64, 32, 32, 3, true>,
                           (const __half*)pAoh, (const __half*)pBvh,
                           (float*)nullptr, (__half*)pWhi,
                           (const float*)nullptr);
    }

    // ---- join: GEMM2 needs both GEMM1 (stream order) and vconv (event) ----
    cudaStreamWaitEvent(0, eJoin, 0);
    {
        dim3 grid(D_DIM / 128, ROWS / 128);
        gemm_nt<128, 64, 64, 3, false><<<grid, 128, SMEM_G2>>>(
            (const __half*)pVh, (const __half*)pWhi,
            out, nullptr, (const float*)pbias);
    }
}

// round 16
// speedup vs baseline: 1.0436x; 1.0436x over previous
#include <cuda_runtime.h>
#include <cuda_fp16.h>
#include <cstdint>
#include <cstddef>

#define D_DIM 1024
#define ROWS  4096   // B*S

// ------------------------- device scratch -------------------------
__device__ __half g_Vh  [ROWS * D_DIM];     // fp16(value)
__device__ __half g_Aoh [D_DIM * D_DIM];    // fp16(Wo)      [m][k]
__device__ __half g_Bvh [D_DIM * D_DIM];    // fp16(Wv^T)    [n][k]
__device__ __half g_Whi [D_DIM * D_DIM];    // fp16(W = Wo@Wv) [n][k]
__device__ float  g_bias[D_DIM];            // Wo@bv + bo

// ------------------------- helpers -------------------------
__device__ __forceinline__ uint32_t smem_u32(const void* p) {
    uint32_t a;
    asm("{ .reg .u64 t; cvta.to.shared.u64 t, %1; cvt.u32.u64 %0, t; }"
        : "=r"(a) : "l"(p));
    return a;
}

__device__ __forceinline__ void ldmatrix_x4(uint32_t* r, uint32_t addr) {
    asm volatile("ldmatrix.sync.aligned.m8n8.x4.shared.b16 {%0,%1,%2,%3}, [%4];"
                 : "=r"(r[0]), "=r"(r[1]), "=r"(r[2]), "=r"(r[3]) : "r"(addr));
}

__device__ __forceinline__ void mma_f16(float* d, const uint32_t* a,
                                        const uint32_t* b) {
    asm volatile(
        "mma.sync.aligned.m16n8k16.row.col.f32.f16.f16.f32 "
        "{%0,%1,%2,%3}, {%4,%5,%6,%7}, {%8,%9}, {%0,%1,%2,%3};"
        : "+f"(d[0]), "+f"(d[1]), "+f"(d[2]), "+f"(d[3])
        : "r"(a[0]), "r"(a[1]), "r"(a[2]), "r"(a[3]), "r"(b[0]), "r"(b[1]));
}

__device__ __forceinline__ void cp_async16(uint32_t dst, const void* src) {
    asm volatile("cp.async.cg.shared.global [%0], [%1], 16;"
                 :: "r"(dst), "l"(src) : "memory");
}

// PDL: allow dependent grid to begin launching (producer side, LATE placement)
__device__ __forceinline__ void pdl_trigger() {
    asm volatile("griddepcontrol.launch_dependents;" ::: "memory");
}
// PDL: block until producer grid's memory is fully visible (consumer side)
__device__ __forceinline__ void pdl_wait() {
    asm volatile("griddepcontrol.wait;" ::: "memory");
}

// ------------------------- fused conversion mega-kernel -------------------
// blockIdx.x partition (256 threads each):  [R9/R13 layout]
//   [0, 1024)     : Wo row convert + bias GEMV          (row = bid)
//   [1024, 2048)  : Wv 32x32 transpose tile             (tile = bid-1024)
//   [2048, 4096)  : V fp32->fp16, 512 float4 per block  (chunk = bid-2048)
__global__ void __launch_bounds__(256)
convert_all(const float* __restrict__ Wo, const float* __restrict__ bv,
            const float* __restrict__ bo, const float* __restrict__ Wv,
            const float* __restrict__ value,
            __half* __restrict__ Aoh, __half* __restrict__ Bvh,
            uint32_t* __restrict__ Vh) {
    __shared__ float sm[33 * 32];     // transpose tile / bias reduction
    const int bid = blockIdx.x;
    const int tid = threadIdx.x;

    if (bid < 1024) {
        // ---- Wo convert + bias GEMV (one row) ----
        const int row = bid;
        float4 a = ((const float4*)(Wo + (size_t)row * D_DIM))[tid];
        float4 b = ((const float4*)bv)[tid];
        __half2 h0(__float2half(a.x), __float2half(a.y));
        __half2 h1(__float2half(a.z), __float2half(a.w));
        uint2 pk = {*reinterpret_cast<uint32_t*>(&h0),
                    *reinterpret_cast<uint32_t*>(&h1)};
        ((uint2*)(Aoh + (size_t)row * D_DIM))[tid] = pk;
        float s = a.x * b.x + a.y * b.y + a.z * b.z + a.w * b.w;
        #pragma unroll
        for (int o = 16; o > 0; o >>= 1)
            s += __shfl_down_sync(0xFFFFFFFFu, s, o);
        if ((tid & 31) == 0) sm[tid >> 5] = s;
        __syncthreads();
        if (tid < 8) {
            s = sm[tid];
            #pragma unroll
            for (int o = 4; o > 0; o >>= 1)
                s += __shfl_down_sync(0xFFu, s, o);
            if (tid == 0) g_bias[row] = s + bo[row];
        }
    } else if (bid < 2048) {
        // ---- Wv[k][n] -> Bvh[n][k] transpose tile ----
        const int t  = bid - 1024;
        const int bx = t & 31, by = t >> 5;
        const int tx = tid & 31, ty = tid >> 5;      // 32 x 8
        const int x = bx * 32 + tx;
        const int y = by * 32;
        #pragma unroll
        for (int j = ty; j < 32; j += 8)
            sm[j * 33 + tx] = Wv[(size_t)(y + j) * D_DIM + x];
        __syncthreads();
        const int ox  = by * 32 + tx;
        const int oyb = bx * 32;
        #pragma unroll
        for (int j = ty; j < 32; j += 8)
            Bvh[(size_t)(oyb + j) * D_DIM + ox] = __float2half(sm[tx * 33 + j]);
    } else {
        // ---- V fp32 -> fp16, 512 float4 per block ----
        const int base = (bid - 2048) * 512 + tid;
        #pragma unroll
        for (int u = 0; u < 2; u++) {
            const int i = base + u * 256;
            float4 x = ((const float4*)value)[i];
            __half2 h0(__float2half(x.x), __float2half(x.y));
            __half2 h1(__float2half(x.z), __float2half(x.w));
            Vh[2 * i]     = *reinterpret_cast<uint32_t*>(&h0);
            Vh[2 * i + 1] = *reinterpret_cast<uint32_t*>(&h1);
        }
    }

    // LATE trigger: dependents (GEMM1) begin launching only as this grid drains.
    pdl_trigger();
}

// ------------------------- NT GEMM (mma.sync fp16, fp32 accum) ------------
// C[m][n] = sum_k A0[m,k] * B0[n,k]
// CTA tile BT x BT; warp tile WM x WN; BK=64; STAGES-deep cp.async.
// SPLITOUT: epilogue writes fp16(result) to Chi instead of fp32 C (+bias).
#define BKK   64
#define PITCH 144                            // 128B payload + 16B pad

template <int BT, int WM, int WN, int STAGES, bool SPLITOUT>
__global__ void __launch_bounds__((BT / WM) * (BT / WN) * 32, 2)
gemm_nt(const __half* __restrict__ A0, const __half* __restrict__ B0,
        float* __restrict__ C, __half* __restrict__ Chi,
        const float* __restrict__ bias) {
    constexpr int NWX     = BT / WN;         // warps along N
    constexpr int MI      = WM / 16;
    constexpr int NI      = WN / 8;
    constexpr int NJ      = WN / 16;
    constexpr int TPB     = BT * PITCH;
    constexpr int STAGE_B = 2 * TPB;
    constexpr int NT      = (BT / WM) * NWX * 32;
    constexpr int CHK     = (BT * 8) / NT;   // 16B chunks / thread / tile
    constexpr int T       = D_DIM / BKK;     // 16 k-tiles

    extern __shared__ __align__(128) char smem[];
    const uint32_t sbase = smem_u32(smem);

    const int tid = threadIdx.x;
    const int wid = tid >> 5;
    const int lid = tid & 31;
    const int wm  = wid / NWX;
    const int wn  = wid % NWX;
    const int m0  = blockIdx.y * BT;
    const int n0  = blockIdx.x * BT;

    const __half* gpA = A0 + (size_t)m0 * D_DIM;
    const __half* gpB = B0 + (size_t)n0 * D_DIM;

    // ldmatrix lane geometry
    const int mat   = lid >> 3;
    const int mrow  = ((mat & 1) << 3) + (lid & 7);
    const int mcolb = (mat >> 1) << 4;

    float acc[MI][NI][4];
    #pragma unroll
    for (int i = 0; i < MI; i++)
        #pragma unroll
        for (int j = 0; j < NI; j++)
            #pragma unroll
            for (int q = 0; q < 4; q++) acc[i][j][q] = 0.f;

    // Consumer side: producer's memory fully visible after this returns.
    pdl_wait();

    auto issue = [&](int t) {
        const uint32_t sb = sbase + (t % STAGES) * STAGE_B;
        const int k0 = t * BKK;
        #pragma unroll
        for (int i = 0; i < CHK; i++) {
            const int c = tid + i * NT;
            const int r = c >> 3, cc = c & 7;
            cp_async16(sb + r * PITCH + cc * 16,
                       gpA + (size_t)r * D_DIM + k0 + cc * 8);
            cp_async16(sb + TPB + r * PITCH + cc * 16,
                       gpB + (size_t)r * D_DIM + k0 + cc * 8);
        }
    };

    #pragma unroll
    for (int t = 0; t < STAGES - 1; t++) {
        issue(t);
        asm volatile("cp.async.commit_group;" ::: "memory");
    }

    for (int t = 0; t < T; t++) {
        asm volatile("cp.async.wait_group %0;" :: "n"(STAGES - 2) : "memory");
        __syncthreads();

        if (t + STAGES - 1 < T) issue(t + STAGES - 1);
        asm volatile("cp.async.commit_group;" ::: "memory");

        const uint32_t bA = sbase + (t % STAGES) * STAGE_B;
        const uint32_t bB = bA + TPB;

        #pragma unroll
        for (int kk = 0; kk < BKK / 16; kk++) {
            uint32_t a0[MI][4];
            uint32_t b0[NI][2];
            #pragma unroll
            for (int mi = 0; mi < MI; mi++) {
                uint32_t roff = (uint32_t)(wm * WM + mi * 16 + mrow) * PITCH +
                                mcolb + kk * 32;
                ldmatrix_x4(a0[mi], bA + roff);
            }
            #pragma unroll
            for (int nj = 0; nj < NJ; nj++) {
                uint32_t roff = (uint32_t)(wn * WN + nj * 16 + mrow) * PITCH +
                                mcolb + kk * 32;
                uint32_t r[4];
                ldmatrix_x4(r, bB + roff);
                b0[nj * 2][0]     = r[0]; b0[nj * 2][1]     = r[2];
                b0[nj * 2 + 1][0] = r[1]; b0[nj * 2 + 1][1] = r[3];
            }
            #pragma unroll
            for (int mi = 0; mi < MI; mi++)
                #pragma unroll
                for (int ni = 0; ni < NI; ni++)
                    mma_f16(acc[mi][ni], a0[mi], b0[ni]);
        }
        __syncthreads();
    }

    // LATE trigger: only the epilogue remains; dependents start launching now.
    pdl_trigger();

    // ---- epilogue ----
    const int trow = lid >> 2;
    const int tcol = (lid & 3) * 2;
    #pragma unroll
    for (int mi = 0; mi < MI; mi++) {
        const int row = m0 + wm * WM + mi * 16 + trow;
        #pragma unroll
        for (int ni = 0; ni < NI; ni++) {
            const int col = n0 + wn * WN + ni * 8 + tcol;
            if (SPLITOUT) {
                #pragma unroll
                for (int h = 0; h < 2; h++) {
                    const int rr = row + h * 8;
                    __half2 hv(__float2half(acc[mi][ni][h * 2 + 0]),
                               __float2half(acc[mi][ni][h * 2 + 1]));
                    *reinterpret_cast<__half2*>(&Chi[(size_t)rr * D_DIM + col]) = hv;
                }
            } else {
                float b0v = bias[col], b1v = bias[col + 1];
                float2 v0 = {acc[mi][ni][0] + b0v, acc[mi][ni][1] + b1v};
                float2 v1 = {acc[mi][ni][2] + b0v, acc[mi][ni][3] + b1v};
                *reinterpret_cast<float2*>(&C[(size_t)row * D_DIM + col]) = v0;
                *reinterpret_cast<float2*>(&C[(size_t)(row + 8) * D_DIM + col]) = v1;
            }
        }
    }
}

// ------------------------- host launcher -------------------------
#define SMEM_G1 (3 * 2 * 64 * PITCH)    // 55296  (3 stages, 2 tiles, BT=64)
#define SMEM_G2 (3 * 2 * 128 * PITCH)   // 110592 (3 stages, 2 tiles, BT=128)

extern "C" void kernel_launch(void* const* d_in, const int* in_sizes, int n_in,
                              void* d_out, int out_size) {
    // 0 query, 1 key, 2 value, 3 mask, 4 Wq, 5 bq, 6 Wk, 7 bk, 8 Wv, 9 bv, 10 Wo, 11 bo
    const float* value = (const float*)d_in[2];
    const float* Wv    = (const float*)d_in[8];
    const float* bv    = (const float*)d_in[9];
    const float* Wo    = (const float*)d_in[10];
    const float* bo    = (const float*)d_in[11];
    float* out = (float*)d_out;

    void *pVh, *pAoh, *pBvh, *pWhi, *pbias;
    cudaGetSymbolAddress(&pVh, g_Vh);
    cudaGetSymbolAddress(&pAoh, g_Aoh);
    cudaGetSymbolAddress(&pBvh, g_Bvh);
    cudaGetSymbolAddress(&pWhi, g_Whi);
    cudaGetSymbolAddress(&pbias, g_bias);

    cudaFuncSetAttribute((const void*)gemm_nt<64, 32, 32, 3, true>,
                         cudaFuncAttributeMaxDynamicSharedMemorySize, SMEM_G1);
    cudaFuncSetAttribute((const void*)gemm_nt<128, 64, 32, 3, false>,
                         cudaFuncAttributeMaxDynamicSharedMemorySize, SMEM_G2);

    // 1) all conversions in one launch (R9 layout)
    convert_all<<<4096, 256>>>(Wo, bv, bo, Wv, value,
                               (__half*)pAoh, (__half*)pBvh, (uint32_t*)pVh);

    // PDL attribute for the two dependent launches
    cudaLaunchAttribute pdlAttr[1];
    pdlAttr[0].id = cudaLaunchAttributeProgrammaticStreamSerialization;
    pdlAttr[0].val.programmaticStreamSerializationAllowed = 1;

    // 2) GEMM1: W = f16(Wo) @ f16(Wv^T)  -> fp16 Whi   (PDL, late trigger)
    {
        cudaLaunchConfig_t cfg = {};
        cfg.gridDim  = dim3(D_DIM / 64, D_DIM / 64, 1);
        cfg.blockDim = dim3(128, 1, 1);
        cfg.dynamicSmemBytes = SMEM_G1;
        cfg.stream = 0;
        cfg.attrs = pdlAttr;
        cfg.numAttrs = 1;
        cudaLaunchKernelEx(&cfg, gemm_nt<64, 32, 32, 3, true>,
                           (const __half*)pAoh, (const __half*)pBvh,
                           (float*)nullptr, (__half*)pWhi,
                           (const float*)nullptr);
    }

    // 3) GEMM2: out = Vh @ Whi^T + bias   (8 warps of 64x32; PDL)
    {
        cudaLaunchConfig_t cfg = {};
        cfg.gridDim  = dim3(D_DIM / 128, ROWS / 128, 1);
        cfg.blockDim = dim3(256, 1, 1);
        cfg.dynamicSmemBytes = SMEM_G2;
        cfg.stream = 0;
        cfg.attrs = pdlAttr;
        cfg.numAttrs = 1;
        cudaLaunchKernelEx(&cfg, gemm_nt<128, 64, 32, 3, false>,
                           (const __half*)pVh, (const __half*)pWhi,
                           out, (__half*)nullptr, (const float*)pbias);
    }
}

// round 17
// speedup vs baseline: 1.0861x; 1.0407x over previous
#include <cuda_runtime.h>
#include <cuda_fp16.h>
#include <cstdint>
#include <cstddef>

#define D_DIM 1024
#define ROWS  4096   // B*S

// ------------------------- device scratch -------------------------
__device__ __half g_Vh  [ROWS * D_DIM];     // fp16(value)
__device__ __half g_Aoh [D_DIM * D_DIM];    // fp16(Wo)      [m][k]
__device__ __half g_Bvh [D_DIM * D_DIM];    // fp16(Wv^T)    [n][k]
__device__ __half g_Whi [D_DIM * D_DIM];    // fp16(W = Wo@Wv) [n][k]
__device__ float  g_bias[D_DIM];            // Wo@bv + bo

// ------------------------- helpers -------------------------
__device__ __forceinline__ uint32_t smem_u32(const void* p) {
    uint32_t a;
    asm("{ .reg .u64 t; cvta.to.shared.u64 t, %1; cvt.u32.u64 %0, t; }"
        : "=r"(a) : "l"(p));
    return a;
}

__device__ __forceinline__ void ldmatrix_x4(uint32_t* r, uint32_t addr) {
    asm volatile("ldmatrix.sync.aligned.m8n8.x4.shared.b16 {%0,%1,%2,%3}, [%4];"
                 : "=r"(r[0]), "=r"(r[1]), "=r"(r[2]), "=r"(r[3]) : "r"(addr));
}

__device__ __forceinline__ void mma_f16(float* d, const uint32_t* a,
                                        const uint32_t* b) {
    asm volatile(
        "mma.sync.aligned.m16n8k16.row.col.f32.f16.f16.f32 "
        "{%0,%1,%2,%3}, {%4,%5,%6,%7}, {%8,%9}, {%0,%1,%2,%3};"
        : "+f"(d[0]), "+f"(d[1]), "+f"(d[2]), "+f"(d[3])
        : "r"(a[0]), "r"(a[1]), "r"(a[2]), "r"(a[3]), "r"(b[0]), "r"(b[1]));
}

__device__ __forceinline__ void cp_async16(uint32_t dst, const void* src) {
    asm volatile("cp.async.cg.shared.global [%0], [%1], 16;"
                 :: "r"(dst), "l"(src) : "memory");
}

// PDL: allow dependent grid to begin launching (producer side, LATE placement)
__device__ __forceinline__ void pdl_trigger() {
    asm volatile("griddepcontrol.launch_dependents;" ::: "memory");
}
// PDL: block until producer grid's memory is fully visible (consumer side)
__device__ __forceinline__ void pdl_wait() {
    asm volatile("griddepcontrol.wait;" ::: "memory");
}

// ------------------------- fused conversion mega-kernel -------------------
// blockIdx.x partition (256 threads each):  [R9/R13 layout]
//   [0, 1024)     : Wo row convert + bias GEMV          (row = bid)
//   [1024, 2048)  : Wv 32x32 transpose tile             (tile = bid-1024)
//   [2048, 4096)  : V fp32->fp16, 512 float4 per block  (chunk = bid-2048)
__global__ void __launch_bounds__(256)
convert_all(const float* __restrict__ Wo, const float* __restrict__ bv,
            const float* __restrict__ bo, const float* __restrict__ Wv,
            const float* __restrict__ value,
            __half* __restrict__ Aoh, __half* __restrict__ Bvh,
            uint32_t* __restrict__ Vh) {
    __shared__ float sm[33 * 32];     // transpose tile / bias reduction
    const int bid = blockIdx.x;
    const int tid = threadIdx.x;

    if (bid < 1024) {
        // ---- Wo convert + bias GEMV (one row) ----
        const int row = bid;
        float4 a = ((const float4*)(Wo + (size_t)row * D_DIM))[tid];
        float4 b = ((const float4*)bv)[tid];
        __half2 h0(__float2half(a.x), __float2half(a.y));
        __half2 h1(__float2half(a.z), __float2half(a.w));
        uint2 pk = {*reinterpret_cast<uint32_t*>(&h0),
                    *reinterpret_cast<uint32_t*>(&h1)};
        ((uint2*)(Aoh + (size_t)row * D_DIM))[tid] = pk;
        float s = a.x * b.x + a.y * b.y + a.z * b.z + a.w * b.w;
        #pragma unroll
        for (int o = 16; o > 0; o >>= 1)
            s += __shfl_down_sync(0xFFFFFFFFu, s, o);
        if ((tid & 31) == 0) sm[tid >> 5] = s;
        __syncthreads();
        if (tid < 8) {
            s = sm[tid];
            #pragma unroll
            for (int o = 4; o > 0; o >>= 1)
                s += __shfl_down_sync(0xFFu, s, o);
            if (tid == 0) g_bias[row] = s + bo[row];
        }
    } else if (bid < 2048) {
        // ---- Wv[k][n] -> Bvh[n][k] transpose tile ----
        const int t  = bid - 1024;
        const int bx = t & 31, by = t >> 5;
        const int tx = tid & 31, ty = tid >> 5;      // 32 x 8
        const int x = bx * 32 + tx;
        const int y = by * 32;
        #pragma unroll
        for (int j = ty; j < 32; j += 8)
            sm[j * 33 + tx] = Wv[(size_t)(y + j) * D_DIM + x];
        __syncthreads();
        const int ox  = by * 32 + tx;
        const int oyb = bx * 32;
        #pragma unroll
        for (int j = ty; j < 32; j += 8)
            Bvh[(size_t)(oyb + j) * D_DIM + ox] = __float2half(sm[tx * 33 + j]);
    } else {
        // ---- V fp32 -> fp16, 512 float4 per block ----
        const int base = (bid - 2048) * 512 + tid;
        #pragma unroll
        for (int u = 0; u < 2; u++) {
            const int i = base + u * 256;
            float4 x = ((const float4*)value)[i];
            __half2 h0(__float2half(x.x), __float2half(x.y));
            __half2 h1(__float2half(x.z), __float2half(x.w));
            Vh[2 * i]     = *reinterpret_cast<uint32_t*>(&h0);
            Vh[2 * i + 1] = *reinterpret_cast<uint32_t*>(&h1);
        }
    }

    // LATE trigger: dependents (GEMM1) begin launching only as this grid drains.
    pdl_trigger();
}

// ------------------------- NT GEMM (mma.sync fp16, fp32 accum) ------------
// C[m][n] = sum_k A0[m,k] * B0[n,k]
// CTA tile BT x BT; warp tile WM x WN; BK=64; STAGES-deep cp.async.
// SPLITOUT: epilogue writes fp16(result) to Chi instead of fp32 C (+bias).
#define BKK   64
#define PITCH 144                            // 128B payload + 16B pad

template <int BT, int WM, int WN, int STAGES, bool SPLITOUT>
__global__ void __launch_bounds__((BT / WM) * (BT / WN) * 32, 2)
gemm_nt(const __half* __restrict__ A0, const __half* __restrict__ B0,
        float* __restrict__ C, __half* __restrict__ Chi,
        const float* __restrict__ bias) {
    constexpr int NWX     = BT / WN;         // warps along N
    constexpr int MI      = WM / 16;
    constexpr int NI      = WN / 8;
    constexpr int NJ      = WN / 16;
    constexpr int TPB     = BT * PITCH;
    constexpr int STAGE_B = 2 * TPB;
    constexpr int NT      = (BT / WM) * NWX * 32;
    constexpr int CHK     = (BT * 8) / NT;   // 16B chunks / thread / tile
    constexpr int T       = D_DIM / BKK;     // 16 k-tiles

    extern __shared__ __align__(128) char smem[];
    const uint32_t sbase = smem_u32(smem);

    const int tid = threadIdx.x;
    const int wid = tid >> 5;
    const int lid = tid & 31;
    const int wm  = wid / NWX;
    const int wn  = wid % NWX;
    const int m0  = blockIdx.y * BT;
    const int n0  = blockIdx.x * BT;

    const __half* gpA = A0 + (size_t)m0 * D_DIM;
    const __half* gpB = B0 + (size_t)n0 * D_DIM;

    // ldmatrix lane geometry
    const int mat   = lid >> 3;
    const int mrow  = ((mat & 1) << 3) + (lid & 7);
    const int mcolb = (mat >> 1) << 4;

    float acc[MI][NI][4];
    #pragma unroll
    for (int i = 0; i < MI; i++)
        #pragma unroll
        for (int j = 0; j < NI; j++)
            #pragma unroll
            for (int q = 0; q < 4; q++) acc[i][j][q] = 0.f;

    // Consumer side: producer's memory fully visible after this returns.
    pdl_wait();

    auto issue = [&](int t) {
        const uint32_t sb = sbase + (t % STAGES) * STAGE_B;
        const int k0 = t * BKK;
        #pragma unroll
        for (int i = 0; i < CHK; i++) {
            const int c = tid + i * NT;
            const int r = c >> 3, cc = c & 7;
            cp_async16(sb + r * PITCH + cc * 16,
                       gpA + (size_t)r * D_DIM + k0 + cc * 8);
            cp_async16(sb + TPB + r * PITCH + cc * 16,
                       gpB + (size_t)r * D_DIM + k0 + cc * 8);
        }
    };

    #pragma unroll
    for (int t = 0; t < STAGES - 1; t++) {
        issue(t);
        asm volatile("cp.async.commit_group;" ::: "memory");
    }

    for (int t = 0; t < T; t++) {
        asm volatile("cp.async.wait_group %0;" :: "n"(STAGES - 2) : "memory");
        __syncthreads();

        if (t + STAGES - 1 < T) issue(t + STAGES - 1);
        asm volatile("cp.async.commit_group;" ::: "memory");

        const uint32_t bA = sbase + (t % STAGES) * STAGE_B;
        const uint32_t bB = bA + TPB;

        #pragma unroll
        for (int kk = 0; kk < BKK / 16; kk++) {
            uint32_t a0[MI][4];
            uint32_t b0[NI][2];
            #pragma unroll
            for (int mi = 0; mi < MI; mi++) {
                uint32_t roff = (uint32_t)(wm * WM + mi * 16 + mrow) * PITCH +
                                mcolb + kk * 32;
                ldmatrix_x4(a0[mi], bA + roff);
            }
            #pragma unroll
            for (int nj = 0; nj < NJ; nj++) {
                uint32_t roff = (uint32_t)(wn * WN + nj * 16 + mrow) * PITCH +
                                mcolb + kk * 32;
                uint32_t r[4];
                ldmatrix_x4(r, bB + roff);
                b0[nj * 2][0]     = r[0]; b0[nj * 2][1]     = r[2];
                b0[nj * 2 + 1][0] = r[1]; b0[nj * 2 + 1][1] = r[3];
            }
            #pragma unroll
            for (int mi = 0; mi < MI; mi++)
                #pragma unroll
                for (int ni = 0; ni < NI; ni++)
                    mma_f16(acc[mi][ni], a0[mi], b0[ni]);
        }
        __syncthreads();
    }

    // LATE trigger: only the epilogue remains; dependents start launching now.
    pdl_trigger();

    // ---- epilogue ----
    const int trow = lid >> 2;
    const int tcol = (lid & 3) * 2;
    #pragma unroll
    for (int mi = 0; mi < MI; mi++) {
        const int row = m0 + wm * WM + mi * 16 + trow;
        #pragma unroll
        for (int ni = 0; ni < NI; ni++) {
            const int col = n0 + wn * WN + ni * 8 + tcol;
            if (SPLITOUT) {
                #pragma unroll
                for (int h = 0; h < 2; h++) {
                    const int rr = row + h * 8;
                    __half2 hv(__float2half(acc[mi][ni][h * 2 + 0]),
                               __float2half(acc[mi][ni][h * 2 + 1]));
                    *reinterpret_cast<__half2*>(&Chi[(size_t)rr * D_DIM + col]) = hv;
                }
            } else {
                float b0v = bias[col], b1v = bias[col + 1];
                float2 v0 = {acc[mi][ni][0] + b0v, acc[mi][ni][1] + b1v};
                float2 v1 = {acc[mi][ni][2] + b0v, acc[mi][ni][3] + b1v};
                *reinterpret_cast<float2*>(&C[(size_t)row * D_DIM + col]) = v0;
                *reinterpret_cast<float2*>(&C[(size_t)(row + 8) * D_DIM + col]) = v1;
            }
        }
    }
}

// ------------------------- host launcher -------------------------
#define SMEM_G64 (3 * 2 * 64 * PITCH)   // 55296 (3 stages, 2 tiles, BT=64)

extern "C" void kernel_launch(void* const* d_in, const int* in_sizes, int n_in,
                              void* d_out, int out_size) {
    // 0 query, 1 key, 2 value, 3 mask, 4 Wq, 5 bq, 6 Wk, 7 bk, 8 Wv, 9 bv, 10 Wo, 11 bo
    const float* value = (const float*)d_in[2];
    const float* Wv    = (const float*)d_in[8];
    const float* bv    = (const float*)d_in[9];
    const float* Wo    = (const float*)d_in[10];
    const float* bo    = (const float*)d_in[11];
    float* out = (float*)d_out;

    void *pVh, *pAoh, *pBvh, *pWhi, *pbias;
    cudaGetSymbolAddress(&pVh, g_Vh);
    cudaGetSymbolAddress(&pAoh, g_Aoh);
    cudaGetSymbolAddress(&pBvh, g_Bvh);
    cudaGetSymbolAddress(&pWhi, g_Whi);
    cudaGetSymbolAddress(&pbias, g_bias);

    cudaFuncSetAttribute((const void*)gemm_nt<64, 32, 32, 3, true>,
                         cudaFuncAttributeMaxDynamicSharedMemorySize, SMEM_G64);
    cudaFuncSetAttribute((const void*)gemm_nt<64, 32, 32, 3, false>,
                         cudaFuncAttributeMaxDynamicSharedMemorySize, SMEM_G64);

    // 1) all conversions in one launch (R9 layout)
    convert_all<<<4096, 256>>>(Wo, bv, bo, Wv, value,
                               (__half*)pAoh, (__half*)pBvh, (uint32_t*)pVh);

    // PDL attribute for the two dependent launches
    cudaLaunchAttribute pdlAttr[1];
    pdlAttr[0].id = cudaLaunchAttributeProgrammaticStreamSerialization;
    pdlAttr[0].val.programmaticStreamSerializationAllowed = 1;

    // 2) GEMM1: W = f16(Wo) @ f16(Wv^T)  -> fp16 Whi   (PDL, late trigger)
    {
        cudaLaunchConfig_t cfg = {};
        cfg.gridDim  = dim3(D_DIM / 64, D_DIM / 64, 1);
        cfg.blockDim = dim3(128, 1, 1);
        cfg.dynamicSmemBytes = SMEM_G64;
        cfg.stream = 0;
        cfg.attrs = pdlAttr;
        cfg.numAttrs = 1;
        cudaLaunchKernelEx(&cfg, gemm_nt<64, 32, 32, 3, true>,
                           (const __half*)pAoh, (const __half*)pBvh,
                           (float*)nullptr, (__half*)pWhi,
                           (const float*)nullptr);
    }

    // 3) GEMM2: out = Vh @ Whi^T + bias   (64x64 tiles, fine-grained balance)
    {
        cudaLaunchConfig_t cfg = {};
        cfg.gridDim  = dim3(D_DIM / 64, ROWS / 64, 1);   // 16 x 64 = 1024 CTAs
        cfg.blockDim = dim3(128, 1, 1);
        cfg.dynamicSmemBytes = SMEM_G64;
        cfg.stream = 0;
        cfg.attrs = pdlAttr;
        cfg.numAttrs = 1;
        cudaLaunchKernelEx(&cfg, gemm_nt<64, 32, 32, 3, false>,
                           (const __half*)pVh, (const __half*)pWhi,
                           out, (__half*)nullptr, (const float*)pbias);
    }
}